// round 11
// baseline (speedup 1.0000x reference)
#include <cuda_runtime.h>
#include <cuda_bf16.h>
#include <cstdint>

// Problem constants (fixed by the reference)
#define NNODES 100000
#define DEG    16
#define FDIM   128
#define HDIM   128
#define ODIM   128
#define BATCH  8192

// Scratch in __device__ globals (no cudaMalloc allowed)
// Pre-split bf16 operands, layout [row][64 kpairs] (uint32 = 2 bf16, even k low)
__device__ uint32_t g_fhi [(size_t)NNODES * 64];   // features hi   25.6 MB
__device__ uint32_t g_flo [(size_t)NNODES * 64];   // features lo   25.6 MB
__device__ uint32_t g_a1hi[(size_t)NNODES * 64];   // agg1 hi       25.6 MB
__device__ uint32_t g_a1lo[(size_t)NNODES * 64];   // agg1 lo       25.6 MB
__device__ float    g_h1  [(size_t)NNODES * HDIM]; // h1 f32        51.2 MB
__device__ uint32_t g_s2hi[(size_t)BATCH * 64];    // h1[nodes] hi   2.1 MB
__device__ uint32_t g_s2lo[(size_t)BATCH * 64];
__device__ uint32_t g_n2hi[(size_t)BATCH * 64];    // mean h1 nbr hi
__device__ uint32_t g_n2lo[(size_t)BATCH * 64];
// Pre-split, transposed weights: [n][128 kpairs]
__device__ uint32_t g_w1t_hi[128 * 128];
__device__ uint32_t g_w1t_lo[128 * 128];
__device__ uint32_t g_w2t_hi[128 * 128];
__device__ uint32_t g_w2t_lo[128 * 128];

// ---------------------------------------------------------------------------
// helpers
// ---------------------------------------------------------------------------
__device__ __forceinline__ uint32_t pack_bf16(float lo, float hi) {
    __nv_bfloat162 h = __floats2bfloat162_rn(lo, hi);   // .x = lo (low 16 bits)
    return *reinterpret_cast<uint32_t*>(&h);
}

__device__ __forceinline__ void split_bf16(float x, float& hf, float& lf) {
    __nv_bfloat16 h = __float2bfloat16_rn(x);
    hf = __bfloat162float(h);
    lf = x - hf;
}

// split a float4 into hi/lo packed uint2 (kpair layout)
__device__ __forceinline__ void split4(float4 v, uint2& hi, uint2& lo) {
    float hx, lx, hy, ly, hz, lz, hw, lw;
    split_bf16(v.x, hx, lx); split_bf16(v.y, hy, ly);
    split_bf16(v.z, hz, lz); split_bf16(v.w, hw, lw);
    hi = make_uint2(pack_bf16(hx, hy), pack_bf16(hz, hw));
    lo = make_uint2(pack_bf16(lx, ly), pack_bf16(lz, lw));
}

__device__ __forceinline__ void mma_bf16(float c[4],
                                         const uint32_t a[4],
                                         uint32_t b0, uint32_t b1) {
    asm volatile(
        "mma.sync.aligned.m16n8k16.row.col.f32.bf16.bf16.f32 "
        "{%0,%1,%2,%3}, {%4,%5,%6,%7}, {%8,%9}, {%0,%1,%2,%3};"
        : "+f"(c[0]), "+f"(c[1]), "+f"(c[2]), "+f"(c[3])
        : "r"(a[0]), "r"(a[1]), "r"(a[2]), "r"(a[3]), "r"(b0), "r"(b1));
}

__device__ __forceinline__ void cp_async16(uint32_t smem_addr, const void* gptr) {
    asm volatile("cp.async.ca.shared.global [%0], [%1], 16;\n"
                 :: "r"(smem_addr), "l"(gptr));
}
__device__ __forceinline__ void cp_async_commit() {
    asm volatile("cp.async.commit_group;\n" ::: "memory");
}
__device__ __forceinline__ void cp_async_wait0() {
    asm volatile("cp.async.wait_group 0;\n" ::: "memory");
}
__device__ __forceinline__ void cp_async_wait1() {
    asm volatile("cp.async.wait_group 1;\n" ::: "memory");
}

// ---------------------------------------------------------------------------
// Weight prep: W[256][128] f32 -> Wt_hi/Wt_lo[n][128 kpairs]
// ---------------------------------------------------------------------------
__global__ __launch_bounds__(256) void prep_w_kernel(
    const float* __restrict__ W, uint32_t* __restrict__ Wt_hi, uint32_t* __restrict__ Wt_lo)
{
    int idx = blockIdx.x * blockDim.x + threadIdx.x;   // 0..16383
    if (idx >= 128 * 128) return;
    int n  = idx >> 7;          // 0..127
    int kp = idx & 127;         // k-pair 0..127
    float x0 = W[(2 * kp + 0) * 128 + n];
    float x1 = W[(2 * kp + 1) * 128 + n];
    float h0, l0, h1, l1;
    split_bf16(x0, h0, l0);
    split_bf16(x1, h1, l1);
    Wt_hi[n * 128 + kp] = pack_bf16(h0, h1);
    Wt_lo[n * 128 + kp] = pack_bf16(l0, l1);
}

// ---------------------------------------------------------------------------
// Layer-1 aggregation + split producer.
// One warp per node i: writes split(features[i]) and split(mean nbr features).
// Self row is an L2 hit (features fully L2-resident from the gathers).
// ---------------------------------------------------------------------------
__global__ __launch_bounds__(256) void agg1_kernel(
    const float4* __restrict__ feat,
    const int*    __restrict__ nbr,
    uint2* __restrict__ fhi,  uint2* __restrict__ flo,
    uint2* __restrict__ a1hi, uint2* __restrict__ a1lo,
    int nrows)
{
    int warp = (blockIdx.x * blockDim.x + threadIdx.x) >> 5;
    int lane = threadIdx.x & 31;
    if (warp >= nrows) return;

    const long long ofs = (long long)warp * 32 + lane;

    // self feature split
    {
        float4 s = feat[ofs];
        uint2 hi, lo;
        split4(s, hi, lo);
        fhi[ofs] = hi;
        flo[ofs] = lo;
    }

    // neighbor mean split
    const int* nb = nbr + (long long)warp * DEG;
    float4 acc = make_float4(0.f, 0.f, 0.f, 0.f);
#pragma unroll
    for (int j = 0; j < DEG; j++) {
        int idx = nb[j];
        float4 v = feat[(long long)idx * 32 + lane];
        acc.x += v.x; acc.y += v.y; acc.z += v.z; acc.w += v.w;
    }
    const float s = 1.0f / (float)DEG;
    acc.x *= s; acc.y *= s; acc.z *= s; acc.w *= s;
    uint2 hi, lo;
    split4(acc, hi, lo);
    a1hi[ofs] = hi;
    a1lo[ofs] = lo;
}

// ---------------------------------------------------------------------------
// Layer-2 aggregation + split producer (batch rows).
// One warp per batch row i: node=nodes[i]; writes split(h1[node]) and
// split(mean h1[nbr[node]]).
// ---------------------------------------------------------------------------
__global__ __launch_bounds__(256) void agg2_kernel(
    const float4* __restrict__ h1,
    const int*    __restrict__ nbr,
    const int*    __restrict__ nodes,
    uint2* __restrict__ shi, uint2* __restrict__ slo,
    uint2* __restrict__ nhi, uint2* __restrict__ nlo,
    int nrows)
{
    int warp = (blockIdx.x * blockDim.x + threadIdx.x) >> 5;
    int lane = threadIdx.x & 31;
    if (warp >= nrows) return;

    int node = nodes[warp];
    const long long ofs = (long long)warp * 32 + lane;

    {
        float4 s = h1[(long long)node * 32 + lane];
        uint2 hi, lo;
        split4(s, hi, lo);
        shi[ofs] = hi;
        slo[ofs] = lo;
    }

    const int* nb = nbr + (long long)node * DEG;
    float4 acc = make_float4(0.f, 0.f, 0.f, 0.f);
#pragma unroll
    for (int j = 0; j < DEG; j++) {
        int idx = nb[j];
        float4 v = h1[(long long)idx * 32 + lane];
        acc.x += v.x; acc.y += v.y; acc.z += v.z; acc.w += v.w;
    }
    const float s = 1.0f / (float)DEG;
    acc.x *= s; acc.y *= s; acc.z *= s; acc.w *= s;
    uint2 hi, lo;
    split4(acc, hi, lo);
    nhi[ofs] = hi;
    nlo[ofs] = lo;
}

// ---------------------------------------------------------------------------
// Tensor-core GEMM, fully-async operand pipeline (all cp.async, pre-split).
// C[M,128] = [A0 | A1] @ W, K=256, bf16 2-term split (3 mma per k16 step).
// A0/A1: [row][64 kpairs] hi+lo; W: [n][128 kpairs] hi+lo.
// Block 128x128, BK=32 (8 k-tiles: t<4 from A0, t>=4 from A1),
// 8 warps (4 M x 2 N), warp tile 32x64, double-buffered smem.
// ---------------------------------------------------------------------------
#define BM  128
#define KT  8            // K tiles (256 / 32)
#define SMS 20           // smem row stride (uint32), conflict-free
#define BUFW (128 * SMS) // words per array per buffer

__global__ __launch_bounds__(256) void gemm_tc_kernel(
    const uint32_t* __restrict__ A0hi, const uint32_t* __restrict__ A0lo,
    const uint32_t* __restrict__ A1hi, const uint32_t* __restrict__ A1lo,
    const uint32_t* __restrict__ Whi,  const uint32_t* __restrict__ Wlo,
    float* __restrict__ C, int M)
{
    extern __shared__ uint32_t smem[];
    uint32_t* as_hi = smem;               // [2][128][SMS]
    uint32_t* as_lo = smem + 2 * BUFW;
    uint32_t* bs_hi = smem + 4 * BUFW;
    uint32_t* bs_lo = smem + 6 * BUFW;
#define ASH(b,r,c) as_hi[(b) * BUFW + (r) * SMS + (c)]
#define ASL(b,r,c) as_lo[(b) * BUFW + (r) * SMS + (c)]
#define BSH(b,r,c) bs_hi[(b) * BUFW + (r) * SMS + (c)]
#define BSL(b,r,c) bs_lo[(b) * BUFW + (r) * SMS + (c)]

    const int tid  = threadIdx.x;
    const int lane = tid & 31;
    const int warp = tid >> 5;
    const int wm   = warp & 3;    // 4 m-tiles of 32 rows
    const int wn   = warp >> 2;   // 2 n-tiles of 64 cols
    const int g    = lane >> 2;
    const int tig  = lane & 3;
    const int block_row = blockIdx.x * BM;

    float acc[2][8][4];
#pragma unroll
    for (int mi = 0; mi < 2; mi++)
#pragma unroll
        for (int ni = 0; ni < 8; ni++)
#pragma unroll
            for (int j = 0; j < 4; j++) acc[mi][ni][j] = 0.f;

    // staging: 2 threads per row; each thread 2 x 16B chunks per array
    const int srow = tid >> 1;           // 0..127 (A row / B col)
    const int q0   = (tid & 1) * 2;      // first 16B chunk (kpairs q*4..q*4+3)

    const int  grow = block_row + srow;
    const bool aok  = (grow < M);
    const uint32_t* a0h = A0hi + (long long)grow * 64;
    const uint32_t* a0l = A0lo + (long long)grow * 64;
    const uint32_t* a1h = A1hi + (long long)grow * 64;
    const uint32_t* a1l = A1lo + (long long)grow * 64;
    const uint32_t* bh  = Whi + srow * 128;
    const uint32_t* bl  = Wlo + srow * 128;

    const uint32_t ash_base = (uint32_t)__cvta_generic_to_shared(&ASH(0, srow, 0));
    const uint32_t asl_base = (uint32_t)__cvta_generic_to_shared(&ASL(0, srow, 0));
    const uint32_t bsh_base = (uint32_t)__cvta_generic_to_shared(&BSH(0, srow, 0));
    const uint32_t bsl_base = (uint32_t)__cvta_generic_to_shared(&BSL(0, srow, 0));

    // stage tile t into buffer b (8 cp.asyncs per thread)
#define STAGE(t, b) do {                                                       \
        const uint32_t* ph = ((t) < 4) ? a0h : a1h;                            \
        const uint32_t* pl = ((t) < 4) ? a0l : a1l;                            \
        const int akb = ((t) & 3) * 16;                                        \
        const int bkb = (t) * 16;                                              \
        _Pragma("unroll")                                                      \
        for (int i = 0; i < 2; i++) {                                          \
            int q = q0 + i;                                                    \
            if (aok) {                                                         \
                cp_async16(ash_base + (b) * BUFW * 4 + q * 16, ph + akb + q * 4);\
                cp_async16(asl_base + (b) * BUFW * 4 + q * 16, pl + akb + q * 4);\
            }                                                                  \
            cp_async16(bsh_base + (b) * BUFW * 4 + q * 16, bh + bkb + q * 4);  \
            cp_async16(bsl_base + (b) * BUFW * 4 + q * 16, bl + bkb + q * 4);  \
        }                                                                      \
    } while (0)

    // ---- prologue: stages 0 and 1 in flight
    STAGE(0, 0);
    cp_async_commit();
    STAGE(1, 1);
    cp_async_commit();
    cp_async_wait1();       // stage 0 landed
    __syncthreads();

    // ---- main loop
    for (int t = 0; t < KT; t++) {
        const int cb = t & 1;

        // compute on buffer cb: 2 k16 steps
#pragma unroll
        for (int kk = 0; kk < 2; kk++) {
            const int kb = kk * 8;
            uint32_t ah[2][4], al[2][4];
#pragma unroll
            for (int mi = 0; mi < 2; mi++) {
                int r = wm * 32 + mi * 16 + g;
                ah[mi][0] = ASH(cb, r,     kb + tig);
                ah[mi][1] = ASH(cb, r + 8, kb + tig);
                ah[mi][2] = ASH(cb, r,     kb + tig + 4);
                ah[mi][3] = ASH(cb, r + 8, kb + tig + 4);
                al[mi][0] = ASL(cb, r,     kb + tig);
                al[mi][1] = ASL(cb, r + 8, kb + tig);
                al[mi][2] = ASL(cb, r,     kb + tig + 4);
                al[mi][3] = ASL(cb, r + 8, kb + tig + 4);
            }
#pragma unroll
            for (int ni = 0; ni < 8; ni++) {
                int c = wn * 64 + ni * 8 + g;
                uint32_t bh0 = BSH(cb, c, kb + tig);
                uint32_t bh1 = BSH(cb, c, kb + tig + 4);
                uint32_t bl0 = BSL(cb, c, kb + tig);
                uint32_t bl1 = BSL(cb, c, kb + tig + 4);
#pragma unroll
                for (int mi = 0; mi < 2; mi++) {
                    mma_bf16(acc[mi][ni], ah[mi], bh0, bh1);
                    mma_bf16(acc[mi][ni], ah[mi], bl0, bl1);
                    mma_bf16(acc[mi][ni], al[mi], bh0, bh1);
                }
            }
        }

        if (t + 1 < KT) {
            __syncthreads();                 // everyone done reading buffer cb
            if (t + 2 < KT) {
                STAGE(t + 2, cb);            // refill cb with tile t+2
                cp_async_commit();
                cp_async_wait1();            // tile t+1 landed
            } else {
                cp_async_wait0();            // last pending: tile t+1
            }
            __syncthreads();                 // publish to all warps
        }
    }

    // ---- epilogue: float2 stores
#pragma unroll
    for (int mi = 0; mi < 2; mi++) {
        int r0 = block_row + wm * 32 + mi * 16 + g;
#pragma unroll
        for (int ni = 0; ni < 8; ni++) {
            int col = wn * 64 + ni * 8 + tig * 2;
            if (r0 < M)
                *reinterpret_cast<float2*>(C + (long long)r0 * ODIM + col) =
                    make_float2(acc[mi][ni][0], acc[mi][ni][1]);
            if (r0 + 8 < M)
                *reinterpret_cast<float2*>(C + (long long)(r0 + 8) * ODIM + col) =
                    make_float2(acc[mi][ni][2], acc[mi][ni][3]);
        }
    }
}

// ---------------------------------------------------------------------------
// kernel_launch
// inputs: 0=features[N,128] f32, 1=w1[256,128] f32, 2=w2[256,128] f32,
//         3=neighbor_idx[N,16] i32, 4=nodes[B] i32 ; out = [B,128] f32
// ---------------------------------------------------------------------------
extern "C" void kernel_launch(void* const* d_in, const int* in_sizes, int n_in,
                              void* d_out, int out_size)
{
    const float* features = (const float*)d_in[0];
    const float* w1       = (const float*)d_in[1];
    const float* w2       = (const float*)d_in[2];
    const int*   nbr      = (const int*)  d_in[3];
    const int*   nodes    = (const int*)  d_in[4];
    float*       out      = (float*)d_out;

    const int N  = in_sizes[0] / FDIM;   // 100000
    const int Bn = in_sizes[4];          // 8192

    uint32_t *fhi, *flo, *a1hi, *a1lo, *s2hi, *s2lo, *n2hi, *n2lo;
    uint32_t *w1t_hi, *w1t_lo, *w2t_hi, *w2t_lo;
    float* h1;
    cudaGetSymbolAddress((void**)&fhi,    g_fhi);
    cudaGetSymbolAddress((void**)&flo,    g_flo);
    cudaGetSymbolAddress((void**)&a1hi,   g_a1hi);
    cudaGetSymbolAddress((void**)&a1lo,   g_a1lo);
    cudaGetSymbolAddress((void**)&h1,     g_h1);
    cudaGetSymbolAddress((void**)&s2hi,   g_s2hi);
    cudaGetSymbolAddress((void**)&s2lo,   g_s2lo);
    cudaGetSymbolAddress((void**)&n2hi,   g_n2hi);
    cudaGetSymbolAddress((void**)&n2lo,   g_n2lo);
    cudaGetSymbolAddress((void**)&w1t_hi, g_w1t_hi);
    cudaGetSymbolAddress((void**)&w1t_lo, g_w1t_lo);
    cudaGetSymbolAddress((void**)&w2t_hi, g_w2t_hi);
    cudaGetSymbolAddress((void**)&w2t_lo, g_w2t_lo);

    const int smem_bytes = 8 * BUFW * 4;   // 81920 B
    static bool attr_set = false;
    if (!attr_set) {
        cudaFuncSetAttribute(gemm_tc_kernel,
                             cudaFuncAttributeMaxDynamicSharedMemorySize, smem_bytes);
        attr_set = true;
    }

    // 0) pre-split/transpose weights
    prep_w_kernel<<<64, 256>>>(w1, w1t_hi, w1t_lo);
    prep_w_kernel<<<64, 256>>>(w2, w2t_hi, w2t_lo);

    // 1) agg1: feature split + neighbor-mean split (f32 gathers, L2-bound)
    agg1_kernel<<<(N + 7) / 8, 256>>>((const float4*)features, nbr,
                                      (uint2*)fhi, (uint2*)flo,
                                      (uint2*)a1hi, (uint2*)a1lo, N);
    // 2) h1 = [features | agg1] @ w1   (fully-async legacy-mma GEMM)
    gemm_tc_kernel<<<(N + BM - 1) / BM, 256, smem_bytes>>>(
        fhi, flo, a1hi, a1lo, w1t_hi, w1t_lo, h1, N);
    // 3) agg2: self-h1 split + neighbor-mean-h1 split over batch nodes
    agg2_kernel<<<(Bn + 7) / 8, 256>>>((const float4*)h1, nbr, nodes,
                                       (uint2*)s2hi, (uint2*)s2lo,
                                       (uint2*)n2hi, (uint2*)n2lo, Bn);
    // 4) out = [h1[nodes] | agg2] @ w2
    gemm_tc_kernel<<<(Bn + BM - 1) / BM, 256, smem_bytes>>>(
        s2hi, s2lo, n2hi, n2lo, w2t_hi, w2t_lo, out, Bn);
}

// round 13
// speedup vs baseline: 1.4028x; 1.4028x over previous
#include <cuda_runtime.h>
#include <cuda_bf16.h>
#include <cstdint>

// Problem constants (fixed by the reference)
#define NNODES 100000
#define DEG    16
#define FDIM   128
#define HDIM   128
#define ODIM   128
#define BATCH  8192

// Scratch in __device__ globals (no cudaMalloc allowed)
// Pre-split bf16 operands, layout [row][64 kpairs] (uint32 = 2 bf16, even k low)
__device__ uint32_t g_fhi [(size_t)NNODES * 64];   // features hi   25.6 MB
__device__ uint32_t g_flo [(size_t)NNODES * 64];   // features lo   25.6 MB
__device__ uint32_t g_a1hi[(size_t)NNODES * 64];   // agg1 hi       25.6 MB
__device__ uint32_t g_a1lo[(size_t)NNODES * 64];   // agg1 lo       25.6 MB
__device__ float    g_h1  [(size_t)NNODES * HDIM]; // h1 f32        51.2 MB
__device__ uint32_t g_s2hi[(size_t)BATCH * 64];    // h1[nodes] hi   2.1 MB
__device__ uint32_t g_s2lo[(size_t)BATCH * 64];
__device__ uint32_t g_n2hi[(size_t)BATCH * 64];    // mean h1 nbr hi
__device__ uint32_t g_n2lo[(size_t)BATCH * 64];
// Pre-split, transposed weights: [n][128 kpairs]
__device__ uint32_t g_w1t_hi[128 * 128];
__device__ uint32_t g_w1t_lo[128 * 128];
__device__ uint32_t g_w2t_hi[128 * 128];
__device__ uint32_t g_w2t_lo[128 * 128];

// ---------------------------------------------------------------------------
// helpers
// ---------------------------------------------------------------------------
__device__ __forceinline__ uint32_t pack_bf16(float lo, float hi) {
    __nv_bfloat162 h = __floats2bfloat162_rn(lo, hi);   // .x = lo (low 16 bits)
    return *reinterpret_cast<uint32_t*>(&h);
}

__device__ __forceinline__ void split_bf16(float x, float& hf, float& lf) {
    __nv_bfloat16 h = __float2bfloat16_rn(x);
    hf = __bfloat162float(h);
    lf = x - hf;
}

// split a float4 into hi/lo packed uint2 (kpair layout)
__device__ __forceinline__ void split4(float4 v, uint2& hi, uint2& lo) {
    float hx, lx, hy, ly, hz, lz, hw, lw;
    split_bf16(v.x, hx, lx); split_bf16(v.y, hy, ly);
    split_bf16(v.z, hz, lz); split_bf16(v.w, hw, lw);
    hi = make_uint2(pack_bf16(hx, hy), pack_bf16(hz, hw));
    lo = make_uint2(pack_bf16(lx, ly), pack_bf16(lz, lw));
}

__device__ __forceinline__ void mma_bf16(float c[4],
                                         const uint32_t a[4],
                                         uint32_t b0, uint32_t b1) {
    asm volatile(
        "mma.sync.aligned.m16n8k16.row.col.f32.bf16.bf16.f32 "
        "{%0,%1,%2,%3}, {%4,%5,%6,%7}, {%8,%9}, {%0,%1,%2,%3};"
        : "+f"(c[0]), "+f"(c[1]), "+f"(c[2]), "+f"(c[3])
        : "r"(a[0]), "r"(a[1]), "r"(a[2]), "r"(a[3]), "r"(b0), "r"(b1));
}

__device__ __forceinline__ void cp_async16(uint32_t smem_addr, const void* gptr) {
    asm volatile("cp.async.ca.shared.global [%0], [%1], 16;\n"
                 :: "r"(smem_addr), "l"(gptr));
}
__device__ __forceinline__ void cp_async_commit() {
    asm volatile("cp.async.commit_group;\n" ::: "memory");
}
__device__ __forceinline__ void cp_async_wait0() {
    asm volatile("cp.async.wait_group 0;\n" ::: "memory");
}

// ---------------------------------------------------------------------------
// Weight prep: W[256][128] f32 -> Wt_hi/Wt_lo[n][128 kpairs]
// ---------------------------------------------------------------------------
__global__ __launch_bounds__(256) void prep_w_kernel(
    const float* __restrict__ W, uint32_t* __restrict__ Wt_hi, uint32_t* __restrict__ Wt_lo)
{
    int idx = blockIdx.x * blockDim.x + threadIdx.x;   // 0..16383
    if (idx >= 128 * 128) return;
    int n  = idx >> 7;          // 0..127
    int kp = idx & 127;         // k-pair 0..127
    float x0 = W[(2 * kp + 0) * 128 + n];
    float x1 = W[(2 * kp + 1) * 128 + n];
    float h0, l0, h1, l1;
    split_bf16(x0, h0, l0);
    split_bf16(x1, h1, l1);
    Wt_hi[n * 128 + kp] = pack_bf16(h0, h1);
    Wt_lo[n * 128 + kp] = pack_bf16(l0, l1);
}

// ---------------------------------------------------------------------------
// Layer-1 aggregation + split producer.
// One warp per node i: writes split(features[i]) and split(mean nbr features).
// ---------------------------------------------------------------------------
__global__ __launch_bounds__(256) void agg1_kernel(
    const float4* __restrict__ feat,
    const int*    __restrict__ nbr,
    uint2* __restrict__ fhi,  uint2* __restrict__ flo,
    uint2* __restrict__ a1hi, uint2* __restrict__ a1lo,
    int nrows)
{
    int warp = (blockIdx.x * blockDim.x + threadIdx.x) >> 5;
    int lane = threadIdx.x & 31;
    if (warp >= nrows) return;

    const long long ofs = (long long)warp * 32 + lane;

    // self feature split (L2-hot row)
    {
        float4 s = feat[ofs];
        uint2 hi, lo;
        split4(s, hi, lo);
        fhi[ofs] = hi;
        flo[ofs] = lo;
    }

    // neighbor mean split
    const int* nb = nbr + (long long)warp * DEG;
    float4 acc = make_float4(0.f, 0.f, 0.f, 0.f);
#pragma unroll
    for (int j = 0; j < DEG; j++) {
        int idx = nb[j];
        float4 v = feat[(long long)idx * 32 + lane];
        acc.x += v.x; acc.y += v.y; acc.z += v.z; acc.w += v.w;
    }
    const float s = 1.0f / (float)DEG;
    acc.x *= s; acc.y *= s; acc.z *= s; acc.w *= s;
    uint2 hi, lo;
    split4(acc, hi, lo);
    a1hi[ofs] = hi;
    a1lo[ofs] = lo;
}

// ---------------------------------------------------------------------------
// Layer-2 aggregation + split producer (batch rows).
// ---------------------------------------------------------------------------
__global__ __launch_bounds__(256) void agg2_kernel(
    const float4* __restrict__ h1,
    const int*    __restrict__ nbr,
    const int*    __restrict__ nodes,
    uint2* __restrict__ shi, uint2* __restrict__ slo,
    uint2* __restrict__ nhi, uint2* __restrict__ nlo,
    int nrows)
{
    int warp = (blockIdx.x * blockDim.x + threadIdx.x) >> 5;
    int lane = threadIdx.x & 31;
    if (warp >= nrows) return;

    int node = nodes[warp];
    const long long ofs = (long long)warp * 32 + lane;

    {
        float4 s = h1[(long long)node * 32 + lane];
        uint2 hi, lo;
        split4(s, hi, lo);
        shi[ofs] = hi;
        slo[ofs] = lo;
    }

    const int* nb = nbr + (long long)node * DEG;
    float4 acc = make_float4(0.f, 0.f, 0.f, 0.f);
#pragma unroll
    for (int j = 0; j < DEG; j++) {
        int idx = nb[j];
        float4 v = h1[(long long)idx * 32 + lane];
        acc.x += v.x; acc.y += v.y; acc.z += v.z; acc.w += v.w;
    }
    const float s = 1.0f / (float)DEG;
    acc.x *= s; acc.y *= s; acc.z *= s; acc.w *= s;
    uint2 hi, lo;
    split4(acc, hi, lo);
    nhi[ofs] = hi;
    nlo[ofs] = lo;
}

// ---------------------------------------------------------------------------
// Tensor-core GEMM: round-5 schedule (prefetch-before-compute, ONE sync/tile,
// wait at tile end) with fully pre-split cp.async operands (no conversion).
// C[M,128] = [A0 | A1] @ W, K=256, bf16 2-term split (3 mma per k16 step).
// Block 128x128, BK=32 (8 k-tiles: t<4 from A0, t>=4 from A1),
// 8 warps (4 M x 2 N), warp tile 32x64, double-buffered smem.
// ---------------------------------------------------------------------------
#define BM  128
#define KT  8            // K tiles (256 / 32)
#define SMS 20           // smem row stride (uint32), conflict-free
#define BUFW (128 * SMS) // words per array per buffer

__global__ __launch_bounds__(256) void gemm_tc_kernel(
    const uint32_t* __restrict__ A0hi, const uint32_t* __restrict__ A0lo,
    const uint32_t* __restrict__ A1hi, const uint32_t* __restrict__ A1lo,
    const uint32_t* __restrict__ Whi,  const uint32_t* __restrict__ Wlo,
    float* __restrict__ C, int M)
{
    extern __shared__ uint32_t smem[];
    uint32_t* as_hi = smem;               // [2][128][SMS]
    uint32_t* as_lo = smem + 2 * BUFW;
    uint32_t* bs_hi = smem + 4 * BUFW;
    uint32_t* bs_lo = smem + 6 * BUFW;
#define ASH(b,r,c) as_hi[(b) * BUFW + (r) * SMS + (c)]
#define ASL(b,r,c) as_lo[(b) * BUFW + (r) * SMS + (c)]
#define BSH(b,r,c) bs_hi[(b) * BUFW + (r) * SMS + (c)]
#define BSL(b,r,c) bs_lo[(b) * BUFW + (r) * SMS + (c)]

    const int tid  = threadIdx.x;
    const int lane = tid & 31;
    const int warp = tid >> 5;
    const int wm   = warp & 3;    // 4 m-tiles of 32 rows
    const int wn   = warp >> 2;   // 2 n-tiles of 64 cols
    const int g    = lane >> 2;
    const int tig  = lane & 3;
    const int block_row = blockIdx.x * BM;

    float acc[2][8][4];
#pragma unroll
    for (int mi = 0; mi < 2; mi++)
#pragma unroll
        for (int ni = 0; ni < 8; ni++)
#pragma unroll
            for (int j = 0; j < 4; j++) acc[mi][ni][j] = 0.f;

    // staging: 2 threads per row; each thread 2 x 16B chunks per array
    const int srow = tid >> 1;           // 0..127 (A row / B col)
    const int q0   = (tid & 1) * 2;      // first 16B chunk (kpairs q*4..q*4+3)

    const int  grow = block_row + srow;
    const bool aok  = (grow < M);
    const uint32_t* a0h = A0hi + (long long)grow * 64;
    const uint32_t* a0l = A0lo + (long long)grow * 64;
    const uint32_t* a1h = A1hi + (long long)grow * 64;
    const uint32_t* a1l = A1lo + (long long)grow * 64;
    const uint32_t* bh  = Whi + srow * 128;
    const uint32_t* bl  = Wlo + srow * 128;

    const uint32_t ash_base = (uint32_t)__cvta_generic_to_shared(&ASH(0, srow, 0));
    const uint32_t asl_base = (uint32_t)__cvta_generic_to_shared(&ASL(0, srow, 0));
    const uint32_t bsh_base = (uint32_t)__cvta_generic_to_shared(&BSH(0, srow, 0));
    const uint32_t bsl_base = (uint32_t)__cvta_generic_to_shared(&BSL(0, srow, 0));

    // stage tile t into buffer b (8 cp.asyncs per thread)
#define STAGE(t, b) do {                                                       \
        const uint32_t* ph = ((t) < 4) ? a0h : a1h;                            \
        const uint32_t* pl = ((t) < 4) ? a0l : a1l;                            \
        const int akb = ((t) & 3) * 16;                                        \
        const int bkb = (t) * 16;                                              \
        _Pragma("unroll")                                                      \
        for (int i = 0; i < 2; i++) {                                          \
            int q = q0 + i;                                                    \
            if (aok) {                                                         \
                cp_async16(ash_base + (b) * BUFW * 4 + q * 16, ph + akb + q * 4);\
                cp_async16(asl_base + (b) * BUFW * 4 + q * 16, pl + akb + q * 4);\
            }                                                                  \
            cp_async16(bsh_base + (b) * BUFW * 4 + q * 16, bh + bkb + q * 4);  \
            cp_async16(bsl_base + (b) * BUFW * 4 + q * 16, bl + bkb + q * 4);  \
        }                                                                      \
    } while (0)

    // ---- prologue: tile 0 into buffer 0, landed and visible
    STAGE(0, 0);
    cp_async_commit();
    cp_async_wait0();
    __syncthreads();

    // ---- main loop: r5 schedule — prefetch first, ONE sync per tile at end
    for (int t = 0; t < KT; t++) {
        const int cb = t & 1;
        const int nb = (t + 1) & 1;
        const bool have_next = (t + 1 < KT);

        if (have_next) {
            STAGE(t + 1, nb);      // in flight during the whole compute phase
            cp_async_commit();
        }

        // compute on buffer cb: 2 k16 steps
#pragma unroll
        for (int kk = 0; kk < 2; kk++) {
            const int kb = kk * 8;
            uint32_t ah[2][4], al[2][4];
#pragma unroll
            for (int mi = 0; mi < 2; mi++) {
                int r = wm * 32 + mi * 16 + g;
                ah[mi][0] = ASH(cb, r,     kb + tig);
                ah[mi][1] = ASH(cb, r + 8, kb + tig);
                ah[mi][2] = ASH(cb, r,     kb + tig + 4);
                ah[mi][3] = ASH(cb, r + 8, kb + tig + 4);
                al[mi][0] = ASL(cb, r,     kb + tig);
                al[mi][1] = ASL(cb, r + 8, kb + tig);
                al[mi][2] = ASL(cb, r,     kb + tig + 4);
                al[mi][3] = ASL(cb, r + 8, kb + tig + 4);
            }
#pragma unroll
            for (int ni = 0; ni < 8; ni++) {
                int c = wn * 64 + ni * 8 + g;
                uint32_t bh0 = BSH(cb, c, kb + tig);
                uint32_t bh1 = BSH(cb, c, kb + tig + 4);
                uint32_t bl0 = BSL(cb, c, kb + tig);
                uint32_t bl1 = BSL(cb, c, kb + tig + 4);
#pragma unroll
                for (int mi = 0; mi < 2; mi++) {
                    mma_bf16(acc[mi][ni], ah[mi], bh0, bh1);
                    mma_bf16(acc[mi][ni], ah[mi], bl0, bl1);
                    mma_bf16(acc[mi][ni], al[mi], bh0, bh1);
                }
            }
        }

        if (have_next) {
            cp_async_wait0();      // tile t+1 landed (had whole compute to fly)
            __syncthreads();       // all warps done reading cb; publish nb
        }
    }

    // ---- epilogue: float2 stores
#pragma unroll
    for (int mi = 0; mi < 2; mi++) {
        int r0 = block_row + wm * 32 + mi * 16 + g;
#pragma unroll
        for (int ni = 0; ni < 8; ni++) {
            int col = wn * 64 + ni * 8 + tig * 2;
            if (r0 < M)
                *reinterpret_cast<float2*>(C + (long long)r0 * ODIM + col) =
                    make_float2(acc[mi][ni][0], acc[mi][ni][1]);
            if (r0 + 8 < M)
                *reinterpret_cast<float2*>(C + (long long)(r0 + 8) * ODIM + col) =
                    make_float2(acc[mi][ni][2], acc[mi][ni][3]);
        }
    }
}

// ---------------------------------------------------------------------------
// kernel_launch
// inputs: 0=features[N,128] f32, 1=w1[256,128] f32, 2=w2[256,128] f32,
//         3=neighbor_idx[N,16] i32, 4=nodes[B] i32 ; out = [B,128] f32
// ---------------------------------------------------------------------------
extern "C" void kernel_launch(void* const* d_in, const int* in_sizes, int n_in,
                              void* d_out, int out_size)
{
    const float* features = (const float*)d_in[0];
    const float* w1       = (const float*)d_in[1];
    const float* w2       = (const float*)d_in[2];
    const int*   nbr      = (const int*)  d_in[3];
    const int*   nodes    = (const int*)  d_in[4];
    float*       out      = (float*)d_out;

    const int N  = in_sizes[0] / FDIM;   // 100000
    const int Bn = in_sizes[4];          // 8192

    uint32_t *fhi, *flo, *a1hi, *a1lo, *s2hi, *s2lo, *n2hi, *n2lo;
    uint32_t *w1t_hi, *w1t_lo, *w2t_hi, *w2t_lo;
    float* h1;
    cudaGetSymbolAddress((void**)&fhi,    g_fhi);
    cudaGetSymbolAddress((void**)&flo,    g_flo);
    cudaGetSymbolAddress((void**)&a1hi,   g_a1hi);
    cudaGetSymbolAddress((void**)&a1lo,   g_a1lo);
    cudaGetSymbolAddress((void**)&h1,     g_h1);
    cudaGetSymbolAddress((void**)&s2hi,   g_s2hi);
    cudaGetSymbolAddress((void**)&s2lo,   g_s2lo);
    cudaGetSymbolAddress((void**)&n2hi,   g_n2hi);
    cudaGetSymbolAddress((void**)&n2lo,   g_n2lo);
    cudaGetSymbolAddress((void**)&w1t_hi, g_w1t_hi);
    cudaGetSymbolAddress((void**)&w1t_lo, g_w1t_lo);
    cudaGetSymbolAddress((void**)&w2t_hi, g_w2t_hi);
    cudaGetSymbolAddress((void**)&w2t_lo, g_w2t_lo);

    const int smem_bytes = 8 * BUFW * 4;   // 81920 B
    static bool attr_set = false;
    if (!attr_set) {
        cudaFuncSetAttribute(gemm_tc_kernel,
                             cudaFuncAttributeMaxDynamicSharedMemorySize, smem_bytes);
        attr_set = true;
    }

    // 0) pre-split/transpose weights
    prep_w_kernel<<<64, 256>>>(w1, w1t_hi, w1t_lo);
    prep_w_kernel<<<64, 256>>>(w2, w2t_hi, w2t_lo);

    // 1) agg1: feature split + neighbor-mean split (f32 gathers, L2-bound)
    agg1_kernel<<<(N + 7) / 8, 256>>>((const float4*)features, nbr,
                                      (uint2*)fhi, (uint2*)flo,
                                      (uint2*)a1hi, (uint2*)a1lo, N);
    // 2) h1 = [features | agg1] @ w1   (async operands, r5 schedule)
    gemm_tc_kernel<<<(N + BM - 1) / BM, 256, smem_bytes>>>(
        fhi, flo, a1hi, a1lo, w1t_hi, w1t_lo, h1, N);
    // 3) agg2: self-h1 split + neighbor-mean-h1 split over batch nodes
    agg2_kernel<<<(Bn + 7) / 8, 256>>>((const float4*)h1, nbr, nodes,
                                       (uint2*)s2hi, (uint2*)s2lo,
                                       (uint2*)n2hi, (uint2*)n2lo, Bn);
    // 4) out = [h1[nodes] | agg2] @ w2
    gemm_tc_kernel<<<(Bn + BM - 1) / BM, 256, smem_bytes>>>(
        s2hi, s2lo, n2hi, n2lo, w2t_hi, w2t_lo, out, Bn);
}

// round 14
// speedup vs baseline: 1.4918x; 1.0634x over previous
#include <cuda_runtime.h>
#include <cuda_bf16.h>
#include <cstdint>

// Problem constants (fixed by the reference)
#define NNODES 100000
#define DEG    16
#define FDIM   128
#define HDIM   128
#define ODIM   128
#define BATCH  8192

// Scratch in __device__ globals (no cudaMalloc allowed).
// Combined hi/lo interleaved bf16 layout per row: for each 2-kpair group g,
// words [4g..4g+3] = { hi(kp 2g), hi(kp 2g+1), lo(kp 2g), lo(kp 2g+1) }.
// A rows: 128 elems -> 64 kpairs -> 32 groups -> 128 words.
__device__ uint32_t g_f  [(size_t)NNODES * 128];   // split features   51.2 MB
__device__ uint32_t g_a1 [(size_t)NNODES * 128];   // split agg1       51.2 MB
__device__ float    g_h1 [(size_t)NNODES * HDIM];  // h1 f32           51.2 MB
__device__ uint32_t g_s2 [(size_t)BATCH  * 128];   // split h1[nodes]   4.2 MB
__device__ uint32_t g_n2 [(size_t)BATCH  * 128];   // split mean-h1-nbr
// Weights transposed+split: row n has 256 elems -> 128 kpairs -> 64 groups
// -> 256 words, same interleaved layout.
__device__ uint32_t g_w1t[128 * 256];
__device__ uint32_t g_w2t[128 * 256];

// ---------------------------------------------------------------------------
// helpers
// ---------------------------------------------------------------------------
__device__ __forceinline__ uint32_t pack_bf16(float lo, float hi) {
    __nv_bfloat162 h = __floats2bfloat162_rn(lo, hi);   // .x = lo (low 16 bits)
    return *reinterpret_cast<uint32_t*>(&h);
}

__device__ __forceinline__ void split_bf16(float x, float& hf, float& lf) {
    __nv_bfloat16 h = __float2bfloat16_rn(x);
    hf = __bfloat162float(h);
    lf = x - hf;
}

// split float4 (elems 4l..4l+3 = kpairs 2l,2l+1) into one interleaved uint4
__device__ __forceinline__ uint4 split4i(float4 v) {
    float hx, lx, hy, ly, hz, lz, hw, lw;
    split_bf16(v.x, hx, lx); split_bf16(v.y, hy, ly);
    split_bf16(v.z, hz, lz); split_bf16(v.w, hw, lw);
    return make_uint4(pack_bf16(hx, hy), pack_bf16(hz, hw),
                      pack_bf16(lx, ly), pack_bf16(lz, lw));
}

__device__ __forceinline__ void mma_bf16(float c[4],
                                         const uint32_t a[4],
                                         uint32_t b0, uint32_t b1) {
    asm volatile(
        "mma.sync.aligned.m16n8k16.row.col.f32.bf16.bf16.f32 "
        "{%0,%1,%2,%3}, {%4,%5,%6,%7}, {%8,%9}, {%0,%1,%2,%3};"
        : "+f"(c[0]), "+f"(c[1]), "+f"(c[2]), "+f"(c[3])
        : "r"(a[0]), "r"(a[1]), "r"(a[2]), "r"(a[3]), "r"(b0), "r"(b1));
}

__device__ __forceinline__ void cp_async16(uint32_t smem_addr, const void* gptr) {
    asm volatile("cp.async.ca.shared.global [%0], [%1], 16;\n"
                 :: "r"(smem_addr), "l"(gptr));
}
__device__ __forceinline__ void cp_async_commit() {
    asm volatile("cp.async.commit_group;\n" ::: "memory");
}
__device__ __forceinline__ void cp_async_wait0() {
    asm volatile("cp.async.wait_group 0;\n" ::: "memory");
}

// ---------------------------------------------------------------------------
// Weight prep: W[256][128] f32 -> Wt[n][256 words] interleaved hi/lo groups.
// One thread per (n, group): group g covers k = 4g..4g+3.
// ---------------------------------------------------------------------------
__global__ __launch_bounds__(256) void prep_w_kernel(
    const float* __restrict__ W, uint4* __restrict__ Wt)
{
    int idx = blockIdx.x * blockDim.x + threadIdx.x;   // 0..8191
    if (idx >= 128 * 64) return;
    int n = idx >> 6;           // 0..127
    int gvi = idx & 63;         // group 0..63
    float4 v = make_float4(W[(4 * gvi + 0) * 128 + n], W[(4 * gvi + 1) * 128 + n],
                           W[(4 * gvi + 2) * 128 + n], W[(4 * gvi + 3) * 128 + n]);
    Wt[n * 64 + gvi] = split4i(v);
}

// ---------------------------------------------------------------------------
// Layer-1 aggregation + split producer.
// One warp per node i: writes split(features[i]) and split(mean nbr features),
// each lane one uint4 (interleaved layout).
// ---------------------------------------------------------------------------
__global__ __launch_bounds__(256) void agg1_kernel(
    const float4* __restrict__ feat,
    const int*    __restrict__ nbr,
    uint4* __restrict__ f, uint4* __restrict__ a1,
    int nrows)
{
    int warp = (blockIdx.x * blockDim.x + threadIdx.x) >> 5;
    int lane = threadIdx.x & 31;
    if (warp >= nrows) return;

    const long long ofs = (long long)warp * 32 + lane;

    // self feature split (L2-hot row)
    f[ofs] = split4i(feat[ofs]);

    // neighbor mean split
    const int* nb = nbr + (long long)warp * DEG;
    float4 acc = make_float4(0.f, 0.f, 0.f, 0.f);
#pragma unroll
    for (int j = 0; j < DEG; j++) {
        int idx = nb[j];
        float4 v = feat[(long long)idx * 32 + lane];
        acc.x += v.x; acc.y += v.y; acc.z += v.z; acc.w += v.w;
    }
    const float s = 1.0f / (float)DEG;
    acc.x *= s; acc.y *= s; acc.z *= s; acc.w *= s;
    a1[ofs] = split4i(acc);
}

// ---------------------------------------------------------------------------
// Layer-2 aggregation + split producer (batch rows).
// ---------------------------------------------------------------------------
__global__ __launch_bounds__(256) void agg2_kernel(
    const float4* __restrict__ h1,
    const int*    __restrict__ nbr,
    const int*    __restrict__ nodes,
    uint4* __restrict__ s2, uint4* __restrict__ n2,
    int nrows)
{
    int warp = (blockIdx.x * blockDim.x + threadIdx.x) >> 5;
    int lane = threadIdx.x & 31;
    if (warp >= nrows) return;

    int node = nodes[warp];
    const long long ofs = (long long)warp * 32 + lane;

    s2[ofs] = split4i(h1[(long long)node * 32 + lane]);

    const int* nb = nbr + (long long)node * DEG;
    float4 acc = make_float4(0.f, 0.f, 0.f, 0.f);
#pragma unroll
    for (int j = 0; j < DEG; j++) {
        int idx = nb[j];
        float4 v = h1[(long long)idx * 32 + lane];
        acc.x += v.x; acc.y += v.y; acc.z += v.z; acc.w += v.w;
    }
    const float s = 1.0f / (float)DEG;
    acc.x *= s; acc.y *= s; acc.z *= s; acc.w *= s;
    n2[ofs] = split4i(acc);
}

// ---------------------------------------------------------------------------
// Tensor-core GEMM: r5/r13 schedule (prefetch-before-compute, one sync/tile),
// LDS.128 fragment loads via k-permuted interleaved hi/lo layout.
// C[M,128] = [A0 | A1] @ W, K=256, bf16 2-term split (3 mma per k16 step).
// Block 128x128, 8 k-tiles of 32, 8 warps (4 M x 2 N), warp tile 32x64.
// Smem row: 32-word payload, stride 48 words (192B) -> LDS.128 conflict-free.
// ---------------------------------------------------------------------------
#define BM   128
#define KT   8                 // K tiles (256 / 32)
#define ROWB 192               // smem row stride in bytes (48 words)
#define BUFB (128 * ROWB)      // one buffer: 24576 B
#define SMEM_TOTAL (4 * BUFB)  // A[2 bufs] + B[2 bufs] = 98304 B

__global__ __launch_bounds__(256) void gemm_tc_kernel(
    const uint32_t* __restrict__ A0, const uint32_t* __restrict__ A1,
    const uint32_t* __restrict__ W,
    float* __restrict__ C, int M)
{
    extern __shared__ char smem[];
    char* as = smem;               // A: buffers 0,1
    char* bs = smem + 2 * BUFB;    // B: buffers 0,1

    const int tid  = threadIdx.x;
    const int lane = tid & 31;
    const int warp = tid >> 5;
    const int wm   = warp & 3;    // 4 m-tiles of 32 rows
    const int wn   = warp >> 2;   // 2 n-tiles of 64 cols
    const int g    = lane >> 2;
    const int tig  = lane & 3;
    const int block_row = blockIdx.x * BM;

    float acc[2][8][4];
#pragma unroll
    for (int mi = 0; mi < 2; mi++)
#pragma unroll
        for (int ni = 0; ni < 8; ni++)
#pragma unroll
            for (int j = 0; j < 4; j++) acc[mi][ni][j] = 0.f;

    // staging: 2 threads per row; each thread 4 x 16B chunks per region
    const int srow = tid >> 1;           // 0..127 (A row / B col)
    const int q0   = (tid & 1) * 4;      // first 16B chunk (of 8 per row-tile)

    const int  grow = block_row + srow;
    const bool aok  = (grow < M);
    const uint32_t* a0p = A0 + (long long)grow * 128;
    const uint32_t* a1p = A1 + (long long)grow * 128;
    const uint32_t* bp  = W + srow * 256;

    const uint32_t as_base = (uint32_t)__cvta_generic_to_shared(as + srow * ROWB);
    const uint32_t bs_base = (uint32_t)__cvta_generic_to_shared(bs + srow * ROWB);

    // stage tile t into buffer b (8 cp.asyncs per thread)
#define STAGE(t, b) do {                                                       \
        const uint32_t* pa = ((t) < 4) ? a0p : a1p;                            \
        const int aw = ((t) & 3) * 32;                                         \
        const int bw = (t) * 32;                                               \
        _Pragma("unroll")                                                      \
        for (int i = 0; i < 4; i++) {                                          \
            int q = q0 + i;                                                    \
            if (aok)                                                           \
                cp_async16(as_base + (b) * BUFB + q * 16, pa + aw + q * 4);    \
            cp_async16(bs_base + (b) * BUFB + q * 16, bp + bw + q * 4);        \
        }                                                                      \
    } while (0)

    // ---- prologue: tile 0 into buffer 0, landed and visible
    STAGE(0, 0);
    cp_async_commit();
    cp_async_wait0();
    __syncthreads();

    // per-thread fragment base offsets (buffer 0, kk=0)
    const char* a_frag = as + (wm * 32 + g) * ROWB + tig * 16;
    const char* b_frag = bs + (wn * 64 + g) * ROWB + tig * 16;

    // ---- main loop: prefetch first, ONE sync per tile at end
    for (int t = 0; t < KT; t++) {
        const int cb = t & 1;
        const int nb = (t + 1) & 1;
        const bool have_next = (t + 1 < KT);

        if (have_next) {
            STAGE(t + 1, nb);      // in flight during the whole compute phase
            cp_async_commit();
        }

        // compute on buffer cb: 2 k16 steps, LDS.128 fragments
#pragma unroll
        for (int kk = 0; kk < 2; kk++) {
            const int off = cb * BUFB + kk * 64;
            uint32_t ah[2][4], al[2][4];
#pragma unroll
            for (int mi = 0; mi < 2; mi++) {
                uint4 v0 = *reinterpret_cast<const uint4*>(a_frag + off + mi * (16 * ROWB));
                uint4 v1 = *reinterpret_cast<const uint4*>(a_frag + off + mi * (16 * ROWB) + 8 * ROWB);
                ah[mi][0] = v0.x; ah[mi][1] = v1.x; ah[mi][2] = v0.y; ah[mi][3] = v1.y;
                al[mi][0] = v0.z; al[mi][1] = v1.z; al[mi][2] = v0.w; al[mi][3] = v1.w;
            }
#pragma unroll
            for (int ni = 0; ni < 8; ni++) {
                uint4 w = *reinterpret_cast<const uint4*>(b_frag + off + ni * (8 * ROWB));
#pragma unroll
                for (int mi = 0; mi < 2; mi++) {
                    mma_bf16(acc[mi][ni], ah[mi], w.x, w.y);
                    mma_bf16(acc[mi][ni], ah[mi], w.z, w.w);
                    mma_bf16(acc[mi][ni], al[mi], w.x, w.y);
                }
            }
        }

        if (have_next) {
            cp_async_wait0();      // tile t+1 landed (had whole compute to fly)
            __syncthreads();       // all warps done reading cb; publish nb
        }
    }

    // ---- epilogue: float2 stores
#pragma unroll
    for (int mi = 0; mi < 2; mi++) {
        int r0 = block_row + wm * 32 + mi * 16 + g;
#pragma unroll
        for (int ni = 0; ni < 8; ni++) {
            int col = wn * 64 + ni * 8 + tig * 2;
            if (r0 < M)
                *reinterpret_cast<float2*>(C + (long long)r0 * ODIM + col) =
                    make_float2(acc[mi][ni][0], acc[mi][ni][1]);
            if (r0 + 8 < M)
                *reinterpret_cast<float2*>(C + (long long)(r0 + 8) * ODIM + col) =
                    make_float2(acc[mi][ni][2], acc[mi][ni][3]);
        }
    }
}

// ---------------------------------------------------------------------------
// kernel_launch
// inputs: 0=features[N,128] f32, 1=w1[256,128] f32, 2=w2[256,128] f32,
//         3=neighbor_idx[N,16] i32, 4=nodes[B] i32 ; out = [B,128] f32
// ---------------------------------------------------------------------------
extern "C" void kernel_launch(void* const* d_in, const int* in_sizes, int n_in,
                              void* d_out, int out_size)
{
    const float* features = (const float*)d_in[0];
    const float* w1       = (const float*)d_in[1];
    const float* w2       = (const float*)d_in[2];
    const int*   nbr      = (const int*)  d_in[3];
    const int*   nodes    = (const int*)  d_in[4];
    float*       out      = (float*)d_out;

    const int N  = in_sizes[0] / FDIM;   // 100000
    const int Bn = in_sizes[4];          // 8192

    uint32_t *f, *a1, *s2, *n2, *w1t, *w2t;
    float* h1;
    cudaGetSymbolAddress((void**)&f,   g_f);
    cudaGetSymbolAddress((void**)&a1,  g_a1);
    cudaGetSymbolAddress((void**)&h1,  g_h1);
    cudaGetSymbolAddress((void**)&s2,  g_s2);
    cudaGetSymbolAddress((void**)&n2,  g_n2);
    cudaGetSymbolAddress((void**)&w1t, g_w1t);
    cudaGetSymbolAddress((void**)&w2t, g_w2t);

    static bool attr_set = false;
    if (!attr_set) {
        cudaFuncSetAttribute(gemm_tc_kernel,
                             cudaFuncAttributeMaxDynamicSharedMemorySize, SMEM_TOTAL);
        attr_set = true;
    }

    // 0) pre-split/transpose weights (interleaved hi/lo groups)
    prep_w_kernel<<<32, 256>>>(w1, (uint4*)w1t);
    prep_w_kernel<<<32, 256>>>(w2, (uint4*)w2t);

    // 1) agg1: feature split + neighbor-mean split (f32 gathers, L2-bound)
    agg1_kernel<<<(N + 7) / 8, 256>>>((const float4*)features, nbr,
                                      (uint4*)f, (uint4*)a1, N);
    // 2) h1 = [features | agg1] @ w1
    gemm_tc_kernel<<<(N + BM - 1) / BM, 256, SMEM_TOTAL>>>(f, a1, w1t, h1, N);
    // 3) agg2: self-h1 split + neighbor-mean-h1 split over batch nodes
    agg2_kernel<<<(Bn + 7) / 8, 256>>>((const float4*)h1, nbr, nodes,
                                       (uint4*)s2, (uint4*)n2, Bn);
    // 4) out = [h1[nodes] | agg2] @ w2
    gemm_tc_kernel<<<(Bn + BM - 1) / BM, 256, SMEM_TOTAL>>>(s2, n2, w2t, out, Bn);
}

// round 16
// speedup vs baseline: 1.7247x; 1.1561x over previous
#include <cuda_runtime.h>
#include <cuda_bf16.h>
#include <cstdint>

// Problem constants (fixed by the reference)
#define NNODES 100000
#define DEG    16
#define FDIM   128
#define HDIM   128
#define ODIM   128
#define BATCH  8192

// Scratch in __device__ globals (no cudaMalloc allowed).
// Interleaved hi/lo bf16 layout per row: group g (k=4g..4g+3) -> words
// [4g..4g+3] = { hi(kp 2g), hi(kp 2g+1), lo(kp 2g), lo(kp 2g+1) }.
__device__ uint32_t g_f  [(size_t)NNODES * 128];   // split features   51.2 MB
__device__ uint32_t g_a1 [(size_t)NNODES * 128];   // split agg1       51.2 MB
__device__ float    g_h1 [(size_t)NNODES * HDIM];  // h1 f32           51.2 MB
__device__ uint32_t g_s2 [(size_t)BATCH  * 128];   // split h1[nodes]   4.2 MB
__device__ uint32_t g_n2 [(size_t)BATCH  * 128];   // split mean-h1-nbr
__device__ uint32_t g_w1t[128 * 256];              // weights, interleaved
__device__ uint32_t g_w2t[128 * 256];
// Active-set machinery
__device__ int g_marks[NNODES];
__device__ int g_list [NNODES];
__device__ int g_count[1];

// ---------------------------------------------------------------------------
// helpers
// ---------------------------------------------------------------------------
__device__ __forceinline__ uint32_t pack_bf16(float lo, float hi) {
    __nv_bfloat162 h = __floats2bfloat162_rn(lo, hi);   // .x = lo (low 16 bits)
    return *reinterpret_cast<uint32_t*>(&h);
}

__device__ __forceinline__ void split_bf16(float x, float& hf, float& lf) {
    __nv_bfloat16 h = __float2bfloat16_rn(x);
    hf = __bfloat162float(h);
    lf = x - hf;
}

// split float4 (elems 4l..4l+3 = kpairs 2l,2l+1) into one interleaved uint4
__device__ __forceinline__ uint4 split4i(float4 v) {
    float hx, lx, hy, ly, hz, lz, hw, lw;
    split_bf16(v.x, hx, lx); split_bf16(v.y, hy, ly);
    split_bf16(v.z, hz, lz); split_bf16(v.w, hw, lw);
    return make_uint4(pack_bf16(hx, hy), pack_bf16(hz, hw),
                      pack_bf16(lx, ly), pack_bf16(lz, lw));
}

__device__ __forceinline__ void mma_bf16(float c[4],
                                         const uint32_t a[4],
                                         uint32_t b0, uint32_t b1) {
    asm volatile(
        "mma.sync.aligned.m16n8k16.row.col.f32.bf16.bf16.f32 "
        "{%0,%1,%2,%3}, {%4,%5,%6,%7}, {%8,%9}, {%0,%1,%2,%3};"
        : "+f"(c[0]), "+f"(c[1]), "+f"(c[2]), "+f"(c[3])
        : "r"(a[0]), "r"(a[1]), "r"(a[2]), "r"(a[3]), "r"(b0), "r"(b1));
}

__device__ __forceinline__ void cp_async16(uint32_t smem_addr, const void* gptr) {
    asm volatile("cp.async.ca.shared.global [%0], [%1], 16;\n"
                 :: "r"(smem_addr), "l"(gptr));
}
__device__ __forceinline__ void cp_async_commit() {
    asm volatile("cp.async.commit_group;\n" ::: "memory");
}
__device__ __forceinline__ void cp_async_wait0() {
    asm volatile("cp.async.wait_group 0;\n" ::: "memory");
}

// ---------------------------------------------------------------------------
// Active-set: mark nodes[] plus their neighbor lists, then compact.
// ---------------------------------------------------------------------------
__global__ __launch_bounds__(256) void mark_kernel(
    const int* __restrict__ nodes, const int* __restrict__ nbr,
    int* __restrict__ marks, int B)
{
    int i = blockIdx.x * blockDim.x + threadIdx.x;
    if (i >= B) return;
    int n = nodes[i];
    marks[n] = 1;
    const int4* nb = reinterpret_cast<const int4*>(nbr + (long long)n * DEG);
#pragma unroll
    for (int j = 0; j < 4; j++) {
        int4 v = nb[j];
        marks[v.x] = 1; marks[v.y] = 1; marks[v.z] = 1; marks[v.w] = 1;
    }
}

__global__ __launch_bounds__(256) void compact_kernel(
    const int* __restrict__ marks, int* __restrict__ list,
    int* __restrict__ count, int n)
{
    int i = blockIdx.x * blockDim.x + threadIdx.x;
    if (i >= n) return;
    if (marks[i]) {
        int p = atomicAdd(count, 1);    // warp-aggregated by ptxas
        list[p] = i;
    }
}

// ---------------------------------------------------------------------------
// Weight prep: W[256][128] f32 -> Wt[n][256 words] interleaved hi/lo groups.
// ---------------------------------------------------------------------------
__global__ __launch_bounds__(256) void prep_w_kernel(
    const float* __restrict__ W, uint4* __restrict__ Wt)
{
    int idx = blockIdx.x * blockDim.x + threadIdx.x;   // 0..8191
    if (idx >= 128 * 64) return;
    int n = idx >> 6;           // 0..127
    int gvi = idx & 63;         // group 0..63
    float4 v = make_float4(W[(4 * gvi + 0) * 128 + n], W[(4 * gvi + 1) * 128 + n],
                           W[(4 * gvi + 2) * 128 + n], W[(4 * gvi + 3) * 128 + n]);
    Wt[n * 64 + gvi] = split4i(v);
}

// ---------------------------------------------------------------------------
// Layer-1 aggregation + split producer over the ACTIVE LIST.
// One warp per list entry: node = list[w]; writes f[node], a1[node].
// ---------------------------------------------------------------------------
__global__ __launch_bounds__(256) void agg1_kernel(
    const float4* __restrict__ feat,
    const int*    __restrict__ nbr,
    const int*    __restrict__ list,
    const int*    __restrict__ count,
    uint4* __restrict__ f, uint4* __restrict__ a1)
{
    int w    = (blockIdx.x * blockDim.x + threadIdx.x) >> 5;
    int lane = threadIdx.x & 31;
    if (w >= *count) return;
    int node = list[w];

    const long long ofs = (long long)node * 32 + lane;

    // self feature split (L2-hot row)
    f[ofs] = split4i(feat[ofs]);

    // neighbor mean split
    const int* nb = nbr + (long long)node * DEG;
    float4 acc = make_float4(0.f, 0.f, 0.f, 0.f);
#pragma unroll
    for (int j = 0; j < DEG; j++) {
        int idx = nb[j];
        float4 v = feat[(long long)idx * 32 + lane];
        acc.x += v.x; acc.y += v.y; acc.z += v.z; acc.w += v.w;
    }
    const float s = 1.0f / (float)DEG;
    acc.x *= s; acc.y *= s; acc.z *= s; acc.w *= s;
    a1[ofs] = split4i(acc);
}

// ---------------------------------------------------------------------------
// Layer-2 aggregation + split producer (batch rows).
// ---------------------------------------------------------------------------
__global__ __launch_bounds__(256) void agg2_kernel(
    const float4* __restrict__ h1,
    const int*    __restrict__ nbr,
    const int*    __restrict__ nodes,
    uint4* __restrict__ s2, uint4* __restrict__ n2,
    int nrows)
{
    int warp = (blockIdx.x * blockDim.x + threadIdx.x) >> 5;
    int lane = threadIdx.x & 31;
    if (warp >= nrows) return;

    int node = nodes[warp];
    const long long ofs = (long long)warp * 32 + lane;

    s2[ofs] = split4i(h1[(long long)node * 32 + lane]);

    const int* nb = nbr + (long long)node * DEG;
    float4 acc = make_float4(0.f, 0.f, 0.f, 0.f);
#pragma unroll
    for (int j = 0; j < DEG; j++) {
        int idx = nb[j];
        float4 v = h1[(long long)idx * 32 + lane];
        acc.x += v.x; acc.y += v.y; acc.z += v.z; acc.w += v.w;
    }
    const float s = 1.0f / (float)DEG;
    acc.x *= s; acc.y *= s; acc.z *= s; acc.w *= s;
    n2[ofs] = split4i(acc);
}

// ---------------------------------------------------------------------------
// Tensor-core GEMM (r14 mainloop): prefetch-before-compute, one sync/tile,
// LDS.128 fragments via k-permuted interleaved hi/lo layout.
// Optional rowlist indirection (gemm1 active set) + dynamic count early-exit.
// C rows scattered through the same rowlist.
// ---------------------------------------------------------------------------
#define BM   128
#define KT   8                 // K tiles (256 / 32)
#define ROWB 192               // smem row stride in bytes (48 words)
#define BUFB (128 * ROWB)      // one buffer: 24576 B
#define SMEM_TOTAL (4 * BUFB)  // A[2 bufs] + B[2 bufs] = 98304 B

__global__ __launch_bounds__(256) void gemm_tc_kernel(
    const uint32_t* __restrict__ A0, const uint32_t* __restrict__ A1,
    const uint32_t* __restrict__ W,
    const int* __restrict__ rowlist, const int* __restrict__ d_count,
    float* __restrict__ C, int M)
{
    const int cnt = d_count ? *d_count : M;
    const int block_row = blockIdx.x * BM;
    if (block_row >= cnt) return;

    extern __shared__ char smem[];
    char* as = smem;               // A: buffers 0,1
    char* bs = smem + 2 * BUFB;    // B: buffers 0,1

    const int tid  = threadIdx.x;
    const int lane = tid & 31;
    const int warp = tid >> 5;
    const int wm   = warp & 3;    // 4 m-tiles of 32 rows
    const int wn   = warp >> 2;   // 2 n-tiles of 64 cols
    const int g    = lane >> 2;
    const int tig  = lane & 3;

    float acc[2][8][4];
#pragma unroll
    for (int mi = 0; mi < 2; mi++)
#pragma unroll
        for (int ni = 0; ni < 8; ni++)
#pragma unroll
            for (int j = 0; j < 4; j++) acc[mi][ni][j] = 0.f;

    // staging: 2 threads per row; each thread 4 x 16B chunks per region
    const int srow = tid >> 1;           // 0..127 (A row / B col)
    const int q0   = (tid & 1) * 4;      // first 16B chunk (of 8 per row-tile)

    const int  gidx = block_row + srow;
    const bool aok  = (gidx < cnt);
    const int  row  = aok ? (rowlist ? rowlist[gidx] : gidx) : 0;
    const uint32_t* a0p = A0 + (long long)row * 128;
    const uint32_t* a1p = A1 + (long long)row * 128;
    const uint32_t* bp  = W + srow * 256;

    const uint32_t as_base = (uint32_t)__cvta_generic_to_shared(as + srow * ROWB);
    const uint32_t bs_base = (uint32_t)__cvta_generic_to_shared(bs + srow * ROWB);

    // stage tile t into buffer b (8 cp.asyncs per thread)
#define STAGE(t, b) do {                                                       \
        const uint32_t* pa = ((t) < 4) ? a0p : a1p;                            \
        const int aw = ((t) & 3) * 32;                                         \
        const int bw = (t) * 32;                                               \
        _Pragma("unroll")                                                      \
        for (int i = 0; i < 4; i++) {                                          \
            int q = q0 + i;                                                    \
            if (aok)                                                           \
                cp_async16(as_base + (b) * BUFB + q * 16, pa + aw + q * 4);    \
            cp_async16(bs_base + (b) * BUFB + q * 16, bp + bw + q * 4);        \
        }                                                                      \
    } while (0)

    // ---- prologue: tile 0 into buffer 0, landed and visible
    STAGE(0, 0);
    cp_async_commit();
    cp_async_wait0();
    __syncthreads();

    // per-thread fragment base offsets (buffer 0, kk=0)
    const char* a_frag = as + (wm * 32 + g) * ROWB + tig * 16;
    const char* b_frag = bs + (wn * 64 + g) * ROWB + tig * 16;

    // ---- main loop: prefetch first, ONE sync per tile at end
    for (int t = 0; t < KT; t++) {
        const int cb = t & 1;
        const int nb = (t + 1) & 1;
        const bool have_next = (t + 1 < KT);

        if (have_next) {
            STAGE(t + 1, nb);      // in flight during the whole compute phase
            cp_async_commit();
        }

        // compute on buffer cb: 2 k16 steps, LDS.128 fragments
#pragma unroll
        for (int kk = 0; kk < 2; kk++) {
            const int off = cb * BUFB + kk * 64;
            uint32_t ah[2][4], al[2][4];
#pragma unroll
            for (int mi = 0; mi < 2; mi++) {
                uint4 v0 = *reinterpret_cast<const uint4*>(a_frag + off + mi * (16 * ROWB));
                uint4 v1 = *reinterpret_cast<const uint4*>(a_frag + off + mi * (16 * ROWB) + 8 * ROWB);
                ah[mi][0] = v0.x; ah[mi][1] = v1.x; ah[mi][2] = v0.y; ah[mi][3] = v1.y;
                al[mi][0] = v0.z; al[mi][1] = v1.z; al[mi][2] = v0.w; al[mi][3] = v1.w;
            }
#pragma unroll
            for (int ni = 0; ni < 8; ni++) {
                uint4 w = *reinterpret_cast<const uint4*>(b_frag + off + ni * (8 * ROWB));
#pragma unroll
                for (int mi = 0; mi < 2; mi++) {
                    mma_bf16(acc[mi][ni], ah[mi], w.x, w.y);
                    mma_bf16(acc[mi][ni], ah[mi], w.z, w.w);
                    mma_bf16(acc[mi][ni], al[mi], w.x, w.y);
                }
            }
        }

        if (have_next) {
            cp_async_wait0();      // tile t+1 landed (had whole compute to fly)
            __syncthreads();       // all warps done reading cb; publish nb
        }
    }

    // ---- epilogue: float2 stores, rows scattered through rowlist
#pragma unroll
    for (int mi = 0; mi < 2; mi++) {
        int i0 = block_row + wm * 32 + mi * 16 + g;
#pragma unroll
        for (int ni = 0; ni < 8; ni++) {
            int col = wn * 64 + ni * 8 + tig * 2;
            if (i0 < cnt) {
                int r = rowlist ? rowlist[i0] : i0;
                *reinterpret_cast<float2*>(C + (long long)r * ODIM + col) =
                    make_float2(acc[mi][ni][0], acc[mi][ni][1]);
            }
            if (i0 + 8 < cnt) {
                int r = rowlist ? rowlist[i0 + 8] : (i0 + 8);
                *reinterpret_cast<float2*>(C + (long long)r * ODIM + col) =
                    make_float2(acc[mi][ni][2], acc[mi][ni][3]);
            }
        }
    }
}

// ---------------------------------------------------------------------------
// kernel_launch
// inputs: 0=features[N,128] f32, 1=w1[256,128] f32, 2=w2[256,128] f32,
//         3=neighbor_idx[N,16] i32, 4=nodes[B] i32 ; out = [B,128] f32
// ---------------------------------------------------------------------------
extern "C" void kernel_launch(void* const* d_in, const int* in_sizes, int n_in,
                              void* d_out, int out_size)
{
    const float* features = (const float*)d_in[0];
    const float* w1       = (const float*)d_in[1];
    const float* w2       = (const float*)d_in[2];
    const int*   nbr      = (const int*)  d_in[3];
    const int*   nodes    = (const int*)  d_in[4];
    float*       out      = (float*)d_out;

    const int N  = in_sizes[0] / FDIM;   // 100000
    const int Bn = in_sizes[4];          // 8192

    uint32_t *f, *a1, *s2, *n2, *w1t, *w2t;
    float* h1;
    int *marks, *list, *count;
    cudaGetSymbolAddress((void**)&f,     g_f);
    cudaGetSymbolAddress((void**)&a1,    g_a1);
    cudaGetSymbolAddress((void**)&h1,    g_h1);
    cudaGetSymbolAddress((void**)&s2,    g_s2);
    cudaGetSymbolAddress((void**)&n2,    g_n2);
    cudaGetSymbolAddress((void**)&w1t,   g_w1t);
    cudaGetSymbolAddress((void**)&w2t,   g_w2t);
    cudaGetSymbolAddress((void**)&marks, g_marks);
    cudaGetSymbolAddress((void**)&list,  g_list);
    cudaGetSymbolAddress((void**)&count, g_count);

    static bool attr_set = false;
    if (!attr_set) {
        cudaFuncSetAttribute(gemm_tc_kernel,
                             cudaFuncAttributeMaxDynamicSharedMemorySize, SMEM_TOTAL);
        attr_set = true;
    }

    // 0a) active-set: clear, mark, compact
    cudaMemsetAsync(marks, 0, (size_t)N * sizeof(int));
    cudaMemsetAsync(count, 0, sizeof(int));
    mark_kernel<<<(Bn + 255) / 256, 256>>>(nodes, nbr, marks, Bn);
    compact_kernel<<<(N + 255) / 256, 256>>>(marks, list, count, N);

    // 0b) pre-split/transpose weights (interleaved hi/lo groups)
    prep_w_kernel<<<32, 256>>>(w1, (uint4*)w1t);
    prep_w_kernel<<<32, 256>>>(w2, (uint4*)w2t);

    // 1) agg1 over active rows: feature split + neighbor-mean split
    agg1_kernel<<<(N + 7) / 8, 256>>>((const float4*)features, nbr,
                                      list, count, (uint4*)f, (uint4*)a1);
    // 2) h1[active] = [features | agg1][active] @ w1
    gemm_tc_kernel<<<(N + BM - 1) / BM, 256, SMEM_TOTAL>>>(
        f, a1, w1t, list, count, h1, N);
    // 3) agg2: self-h1 split + neighbor-mean-h1 split over batch nodes
    agg2_kernel<<<(Bn + 7) / 8, 256>>>((const float4*)h1, nbr, nodes,
                                       (uint4*)s2, (uint4*)n2, Bn);
    // 4) out = [h1[nodes] | agg2] @ w2
    gemm_tc_kernel<<<(Bn + BM - 1) / BM, 256, SMEM_TOTAL>>>(
        s2, n2, w2t, nullptr, nullptr, out, Bn);
}